// round 2
// baseline (speedup 1.0000x reference)
#include <cuda_runtime.h>
#include <math.h>

#define B_SZ   1024
#define HID    384
#define MH     300
#define OPAD   304

// Scratch (device globals; allocations forbidden)
__device__ float g_s1[B_SZ * HID];
__device__ float g_s2[B_SZ * HID];
__device__ float g_Axb[B_SZ * OPAD];   // Ax + b1 (padded stride)
__device__ float g_By [B_SZ * OPAD];
__device__ float g_klpart[B_SZ];
__device__ float g_T0[B_SZ];
__device__ float g_rowpart[16 * B_SZ]; // per (j-tile, i) partial sums of exp(u)

__device__ __forceinline__ float softplusf(float x) {
    return fmaxf(x, 0.f) + log1pf(expf(-fabsf(x)));
}

// ---------------------------------------------------------------------------
// K1: per-batch-row fused  einsum -> (mu,sig) -> sample -> KL partial
// ---------------------------------------------------------------------------
__global__ __launch_bounds__(256) void k1_fuse(
    const float* __restrict__ zl, const float* __restrict__ zv,
    const float* __restrict__ wl_g, const float* __restrict__ bl_g,
    const float* __restrict__ wv_g, const float* __restrict__ bv_g,
    const float* __restrict__ eps1, const float* __restrict__ eps2)
{
    __shared__ float z1s[768], z2s[768], wls[20], wvs[36], red[256];
    const int b = blockIdx.x, t = threadIdx.x;
    if (t < 20) wls[t] = wl_g[t];
    if (t < 36) wvs[t] = wv_g[t];
    __syncthreads();
    const float bl = bl_g[0], bv = bv_g[0];
    {
        const float* p = zl + (size_t)b * 20 * 768;
        float a0 = bl, a1 = bl, a2 = bl;
        #pragma unroll
        for (int s = 0; s < 20; ++s) {
            float w = wls[s];
            a0 = fmaf(p[s*768 + t      ], w, a0);
            a1 = fmaf(p[s*768 + t + 256], w, a1);
            a2 = fmaf(p[s*768 + t + 512], w, a2);
        }
        z1s[t] = a0; z1s[t + 256] = a1; z1s[t + 512] = a2;
    }
    {
        const float* p = zv + (size_t)b * 36 * 768;
        float a0 = bv, a1 = bv, a2 = bv;
        #pragma unroll
        for (int s = 0; s < 36; ++s) {
            float w = wvs[s];
            a0 = fmaf(p[s*768 + t      ], w, a0);
            a1 = fmaf(p[s*768 + t + 256], w, a1);
            a2 = fmaf(p[s*768 + t + 512], w, a2);
        }
        z2s[t] = a0; z2s[t + 256] = a1; z2s[t + 512] = a2;
    }
    __syncthreads();
    float klacc = 0.f;
    for (int k = t; k < HID; k += 256) {
        float mu1 = z1s[k], mu2 = z2s[k];
        float sg1 = softplusf(z1s[k + HID]) + 1e-7f;
        float sg2 = softplusf(z2s[k + HID]) + 1e-7f;
        float e1 = eps1[b * HID + k], e2 = eps2[b * HID + k];
        float s1v = fmaf(sg1, e1, mu1);
        float s2v = fmaf(sg2, e2, mu2);
        g_s1[b * HID + k] = s1v;
        g_s2[b * HID + k] = s2v;
        float d1 = (s1v - mu2) / sg2;
        float d2 = (s2v - mu1) / sg1;
        // (kl12 + kl21) per-dim with exact log-sigma cancellation
        klacc += 0.5f * (d1*d1 + d2*d2 - e1*e1 - e2*e2);
    }
    red[t] = klacc;
    __syncthreads();
    for (int s = 128; s > 0; s >>= 1) {
        if (t < s) red[t] += red[t + s];
        __syncthreads();
    }
    if (t == 0) g_klpart[b] = red[0];
}

// ---------------------------------------------------------------------------
// K2: Axb = s1 @ W1x^T + b1 ;  By = s2 @ W1y^T
// grid (16, 5, 2), block 256.  BM=64, BN=64 (300 padded to 320), BK=32.
// ---------------------------------------------------------------------------
__global__ __launch_bounds__(256) void k2_gemm(
    const float* __restrict__ W1, const float* __restrict__ b1)
{
    __shared__ float As[64][33];
    __shared__ float Ws[64][33];

    const int z  = blockIdx.z;
    const int r0 = blockIdx.x * 64;
    const int c0 = blockIdx.y * 64;
    const float* S = z ? g_s2 : g_s1;
    float*       O = z ? g_By : g_Axb;
    const int koff = z ? HID : 0;

    const int t  = threadIdx.x;
    const int tx = t & 15;    // col group
    const int ty = t >> 4;    // row group

    float acc[4][4];
    #pragma unroll
    for (int i = 0; i < 4; ++i)
        #pragma unroll
        for (int j = 0; j < 4; ++j) acc[i][j] = 0.f;

    for (int kk = 0; kk < HID; kk += 32) {
        __syncthreads();
        #pragma unroll
        for (int i = 0; i < 8; ++i) {
            int e = t + i * 256;
            int r = e >> 5, k = e & 31;
            As[r][k] = S[(r0 + r) * HID + kk + k];
        }
        #pragma unroll
        for (int i = 0; i < 8; ++i) {
            int e = t + i * 256;
            int r = e >> 5, k = e & 31;
            int col = c0 + r;
            Ws[r][k] = (col < MH) ? W1[col * 768 + koff + kk + k] : 0.f;
        }
        __syncthreads();
        #pragma unroll 8
        for (int k = 0; k < 32; ++k) {
            float a[4], w[4];
            #pragma unroll
            for (int r = 0; r < 4; ++r) a[r] = As[ty*4 + r][k];
            #pragma unroll
            for (int c = 0; c < 4; ++c) w[c] = Ws[tx*4 + c][k];
            #pragma unroll
            for (int r = 0; r < 4; ++r)
                #pragma unroll
                for (int c = 0; c < 4; ++c)
                    acc[r][c] = fmaf(a[r], w[c], acc[r][c]);
        }
    }
    #pragma unroll
    for (int r = 0; r < 4; ++r) {
        int row = r0 + ty*4 + r;
        #pragma unroll
        for (int c = 0; c < 4; ++c) {
            int col = c0 + tx*4 + c;
            if (col < MH) {
                float v = acc[r][c];
                if (z == 0) v += b1[col];
                O[row * OPAD + col] = v;
            }
        }
    }
}

// ---------------------------------------------------------------------------
// K3: pairwise grid.  u[i][j] = sum_k relu(Axb[j,k] + By[perm[i],k]) * w2[k]
// accumulate sum_j exp(u + b2) per i, per j-tile (deterministic partials).
// grid (16 j-tiles, 8 i-tiles), block 256.  Tile 128(i) x 64(j), 8x4/thread.
// ---------------------------------------------------------------------------
__global__ __launch_bounds__(256) void k3_pair(
    const int* __restrict__ perm, const float* __restrict__ W2,
    const float* __restrict__ b2g)
{
    __shared__ float Bys[128][33];
    __shared__ float Axs[64][33];
    __shared__ float w2s[320];
    __shared__ int   permS[128];
    __shared__ float rowred[128][17];

    const int jt = blockIdx.x;   // 0..15
    const int it = blockIdx.y;   // 0..7
    const int i0 = it * 128, j0 = jt * 64;
    const int t  = threadIdx.x;
    const int tj = t & 15;       // j group  (x4)
    const int ti = t >> 4;       // i group  (x8)

    if (t < 128) permS[t] = perm[i0 + t];
    for (int k = t; k < 320; k += 256) w2s[k] = (k < MH) ? W2[k] : 0.f;

    float acc[8][4];
    #pragma unroll
    for (int r = 0; r < 8; ++r)
        #pragma unroll
        for (int c = 0; c < 4; ++c) acc[r][c] = 0.f;

    for (int kk = 0; kk < 320; kk += 32) {
        __syncthreads();
        #pragma unroll
        for (int i = 0; i < 16; ++i) {
            int e = t + i * 256;
            int r = e >> 5, k = e & 31;
            int gk = kk + k;
            Bys[r][k] = (gk < MH) ? g_By[permS[r] * OPAD + gk] : 0.f;
        }
        #pragma unroll
        for (int i = 0; i < 8; ++i) {
            int e = t + i * 256;
            int r = e >> 5, k = e & 31;
            int gk = kk + k;
            Axs[r][k] = (gk < MH) ? g_Axb[(j0 + r) * OPAD + gk] : 0.f;
        }
        __syncthreads();
        #pragma unroll 4
        for (int k = 0; k < 32; ++k) {
            float a[4], b[8];
            #pragma unroll
            for (int c = 0; c < 4; ++c) a[c] = Axs[tj*4 + c][k];
            #pragma unroll
            for (int r = 0; r < 8; ++r) b[r] = Bys[ti*8 + r][k];
            float w = w2s[kk + k];
            #pragma unroll
            for (int r = 0; r < 8; ++r)
                #pragma unroll
                for (int c = 0; c < 4; ++c)
                    acc[r][c] = fmaf(fmaxf(a[c] + b[r], 0.f), w, acc[r][c]);
        }
    }

    const float b2v = b2g[0];
    __syncthreads();
    #pragma unroll
    for (int r = 0; r < 8; ++r) {
        float s = expf(acc[r][0] + b2v) + expf(acc[r][1] + b2v)
                + expf(acc[r][2] + b2v) + expf(acc[r][3] + b2v);
        rowred[ti*8 + r][tj] = s;
    }
    __syncthreads();
    if (t < 128) {
        float s = 0.f;
        #pragma unroll
        for (int c = 0; c < 16; ++c) s += rowred[t][c];
        g_rowpart[jt * B_SZ + i0 + t] = s;
    }
}

// ---------------------------------------------------------------------------
// K4: T0[b] = softplus( relu(Axb[b]+By[b]) . w2 + b2 )
// grid 128, block 256 (8 warps = 8 rows/block)
// ---------------------------------------------------------------------------
__global__ __launch_bounds__(256) void k4_t0(
    const float* __restrict__ W2, const float* __restrict__ b2g)
{
    const int t = threadIdx.x;
    const int w = t >> 5, l = t & 31;
    const int b = blockIdx.x * 8 + w;
    float u = 0.f;
    for (int k = l; k < MH; k += 32) {
        float v = g_Axb[b * OPAD + k] + g_By[b * OPAD + k];
        u = fmaf(fmaxf(v, 0.f), W2[k], u);
    }
    #pragma unroll
    for (int off = 16; off > 0; off >>= 1)
        u += __shfl_xor_sync(0xFFFFFFFFu, u, off);
    if (l == 0) g_T0[b] = softplusf(u + b2g[0]);
}

// ---------------------------------------------------------------------------
// K5: final scalar reduction (double accumulators)
// ---------------------------------------------------------------------------
__global__ __launch_bounds__(256) void k5_final(float* __restrict__ out)
{
    __shared__ double skl[256], st0[256], sL[256];
    const int t = threadIdx.x;
    double kl = 0.0, t0 = 0.0, L = 0.0;
    for (int i = t; i < B_SZ; i += 256) {
        kl += (double)g_klpart[i];
        t0 += (double)g_T0[i];
        float rs = 0.f;
        #pragma unroll
        for (int jt = 0; jt < 16; ++jt) rs += g_rowpart[jt * B_SZ + i];
        // logsumexp_j softplus(u) = log(B + sum_j e^u)
        L += log((double)B_SZ + (double)rs);
    }
    skl[t] = kl; st0[t] = t0; sL[t] = L;
    __syncthreads();
    for (int s = 128; s > 0; s >>= 1) {
        if (t < s) { skl[t] += skl[t+s]; st0[t] += st0[t+s]; sL[t] += sL[t+s]; }
        __syncthreads();
    }
    if (t == 0) {
        double d_skl = skl[0] / (double)B_SZ * 0.5;
        double t0m   = st0[0] / (double)B_SZ;
        double meanL = sL[0] / (double)B_SZ;
        double lower = t0m - (meanL - log((double)B_SZ));
        out[0] = (float)(d_skl - lower);
    }
}

// ---------------------------------------------------------------------------
extern "C" void kernel_launch(void* const* d_in, const int* in_sizes, int n_in,
                              void* d_out, int out_size)
{
    const float* zl    = (const float*)d_in[0];
    const float* zv    = (const float*)d_in[1];
    const float* fclw  = (const float*)d_in[2];
    const float* fclb  = (const float*)d_in[3];
    const float* fcvw  = (const float*)d_in[4];
    const float* fcvb  = (const float*)d_in[5];
    const float* W1    = (const float*)d_in[6];
    const float* b1    = (const float*)d_in[7];
    const float* W2    = (const float*)d_in[8];
    const float* b2    = (const float*)d_in[9];
    const float* eps1  = (const float*)d_in[10];
    const float* eps2  = (const float*)d_in[11];
    const int*   perm  = (const int*)d_in[12];
    float* out = (float*)d_out;

    k1_fuse<<<B_SZ, 256>>>(zl, zv, fclw, fclb, fcvw, fcvb, eps1, eps2);
    k2_gemm<<<dim3(16, 5, 2), 256>>>(W1, b1);
    k3_pair<<<dim3(16, 8), 256>>>(perm, W2, b2);
    k4_t0<<<128, 256>>>(W2, b2);
    k5_final<<<1, 256>>>(out);
}

// round 3
// speedup vs baseline: 1.1565x; 1.1565x over previous
#include <cuda_runtime.h>
#include <math.h>

#define B_SZ   1024
#define HID    384
#define MH     300
#define OPAD   304

// Scratch (device globals; allocations forbidden). Zero-initialized at load.
__device__ float g_s1[B_SZ * HID];
__device__ float g_s2[B_SZ * HID];
__device__ float g_Axb[B_SZ * OPAD];
__device__ float g_By [B_SZ * OPAD];
__device__ float g_klpart[B_SZ];
__device__ float g_T0[B_SZ];
__device__ float g_rowpart[16 * B_SZ];

__device__ __forceinline__ float softplusf(float x) {
    return fmaxf(x, 0.f) + log1pf(expf(-fabsf(x)));
}

// Packed f32x2 helpers (Blackwell FADD2/FFMA2 — only reachable via PTX)
__device__ __forceinline__ float2 f2add(float2 a, float2 b) {
    float2 d;
    asm("{\n\t"
        ".reg .b64 ra, rb, rd;\n\t"
        "mov.b64 ra, {%2, %3};\n\t"
        "mov.b64 rb, {%4, %5};\n\t"
        "add.rn.f32x2 rd, ra, rb;\n\t"
        "mov.b64 {%0, %1}, rd;\n\t"
        "}" : "=f"(d.x), "=f"(d.y)
            : "f"(a.x), "f"(a.y), "f"(b.x), "f"(b.y));
    return d;
}
__device__ __forceinline__ float2 f2fma(float2 a, float2 b, float2 c) {
    float2 d;
    asm("{\n\t"
        ".reg .b64 ra, rb, rc, rd;\n\t"
        "mov.b64 ra, {%2, %3};\n\t"
        "mov.b64 rb, {%4, %5};\n\t"
        "mov.b64 rc, {%6, %7};\n\t"
        "fma.rn.f32x2 rd, ra, rb, rc;\n\t"
        "mov.b64 {%0, %1}, rd;\n\t"
        "}" : "=f"(d.x), "=f"(d.y)
            : "f"(a.x), "f"(a.y), "f"(b.x), "f"(b.y), "f"(c.x), "f"(c.y));
    return d;
}

// ---------------------------------------------------------------------------
// K1: per-batch-row fused  einsum -> (mu,sig) -> sample -> KL partial
// grid 1024, block 192 (one float4 column chunk per thread). HBM-bound.
// ---------------------------------------------------------------------------
__global__ __launch_bounds__(192) void k1_fuse(
    const float* __restrict__ zl, const float* __restrict__ zv,
    const float* __restrict__ wl_g, const float* __restrict__ bl_g,
    const float* __restrict__ wv_g, const float* __restrict__ bv_g,
    const float* __restrict__ eps1, const float* __restrict__ eps2)
{
    __shared__ float z1s[768], z2s[768];
    __shared__ float wls[20], wvs[36];
    __shared__ float redw[6];
    const int b = blockIdx.x, t = threadIdx.x;
    if (t < 20) wls[t] = wl_g[t];
    if (t >= 32 && t < 68) wvs[t - 32] = wv_g[t - 32];
    __syncthreads();
    const float bl = bl_g[0], bv = bv_g[0];
    {
        const float4* p = (const float4*)(zl + (size_t)b * 20 * 768) + t;
        float4 a = make_float4(bl, bl, bl, bl);
        #pragma unroll
        for (int s = 0; s < 20; ++s) {
            float4 v = p[s * 192];
            float w = wls[s];
            a.x = fmaf(v.x, w, a.x); a.y = fmaf(v.y, w, a.y);
            a.z = fmaf(v.z, w, a.z); a.w = fmaf(v.w, w, a.w);
        }
        ((float4*)z1s)[t] = a;
    }
    {
        const float4* p = (const float4*)(zv + (size_t)b * 36 * 768) + t;
        float4 a = make_float4(bv, bv, bv, bv);
        #pragma unroll
        for (int s = 0; s < 36; ++s) {
            float4 v = p[s * 192];
            float w = wvs[s];
            a.x = fmaf(v.x, w, a.x); a.y = fmaf(v.y, w, a.y);
            a.z = fmaf(v.z, w, a.z); a.w = fmaf(v.w, w, a.w);
        }
        ((float4*)z2s)[t] = a;
    }
    __syncthreads();
    float klacc = 0.f;
    #pragma unroll
    for (int q = 0; q < 2; ++q) {
        int k = t + q * 192;
        float mu1 = z1s[k], mu2 = z2s[k];
        float sg1 = softplusf(z1s[k + HID]) + 1e-7f;
        float sg2 = softplusf(z2s[k + HID]) + 1e-7f;
        float e1 = eps1[b * HID + k], e2 = eps2[b * HID + k];
        float s1v = fmaf(sg1, e1, mu1);
        float s2v = fmaf(sg2, e2, mu2);
        g_s1[b * HID + k] = s1v;
        g_s2[b * HID + k] = s2v;
        float d1 = (s1v - mu2) / sg2;
        float d2 = (s2v - mu1) / sg1;
        klacc += 0.5f * (d1 * d1 + d2 * d2 - e1 * e1 - e2 * e2);
    }
    #pragma unroll
    for (int off = 16; off > 0; off >>= 1)
        klacc += __shfl_xor_sync(0xFFFFFFFFu, klacc, off);
    if ((t & 31) == 0) redw[t >> 5] = klacc;
    __syncthreads();
    if (t == 0) {
        float s = redw[0] + redw[1] + redw[2] + redw[3] + redw[4] + redw[5];
        g_klpart[b] = s;
    }
}

// ---------------------------------------------------------------------------
// K2: Axb = s1 @ W1x^T + b1 ;  By = s2 @ W1y^T
// grid (16,5,2), block 256.  Tile 64x64, packed f32x2 over k, 4x4/thread.
// ---------------------------------------------------------------------------
__global__ __launch_bounds__(256) void k2_gemm(
    const float* __restrict__ W1, const float* __restrict__ b1)
{
    __shared__ float2 As[64][17];
    __shared__ float2 Ws[64][17];

    const int z  = blockIdx.z;
    const int r0 = blockIdx.x * 64;
    const int c0 = blockIdx.y * 64;
    const float* S = z ? g_s2 : g_s1;
    float*       O = z ? g_By : g_Axb;
    const int koff = z ? HID : 0;

    const int t  = threadIdx.x;
    const int tj = t & 15;   // col sub (stride-16 interleave)
    const int ti = t >> 4;   // row sub

    float2 acc[4][4];
    #pragma unroll
    for (int r = 0; r < 4; ++r)
        #pragma unroll
        for (int c = 0; c < 4; ++c) acc[r][c] = make_float2(0.f, 0.f);

    for (int kk2 = 0; kk2 < 192; kk2 += 16) {
        __syncthreads();
        #pragma unroll
        for (int i = 0; i < 4; ++i) {
            int e = t + i * 256;
            int row = e >> 4, k2 = e & 15;
            As[row][k2] = *(const float2*)&S[(r0 + row) * HID + (kk2 + k2) * 2];
            int col = c0 + row;
            Ws[row][k2] = (col < MH)
                ? *(const float2*)&W1[col * 768 + koff + (kk2 + k2) * 2]
                : make_float2(0.f, 0.f);
        }
        __syncthreads();
        #pragma unroll 4
        for (int k2 = 0; k2 < 16; ++k2) {
            float2 a[4], w[4];
            #pragma unroll
            for (int r = 0; r < 4; ++r) a[r] = As[ti + 16 * r][k2];
            #pragma unroll
            for (int c = 0; c < 4; ++c) w[c] = Ws[tj + 16 * c][k2];
            #pragma unroll
            for (int r = 0; r < 4; ++r)
                #pragma unroll
                for (int c = 0; c < 4; ++c)
                    acc[r][c] = f2fma(a[r], w[c], acc[r][c]);
        }
    }
    #pragma unroll
    for (int r = 0; r < 4; ++r) {
        int row = r0 + ti + 16 * r;
        #pragma unroll
        for (int c = 0; c < 4; ++c) {
            int col = c0 + tj + 16 * c;
            if (col < MH) {
                float v = acc[r][c].x + acc[r][c].y;
                if (z == 0) v += b1[col];
                O[row * OPAD + col] = v;
            }
        }
    }
}

// ---------------------------------------------------------------------------
// K3: pairwise grid.  u[i][j] = sum_k relu(Axb[j,k] + By[perm[i],k]) * w2[k]
// per-i, per-jtile partial sums of exp(u+b2).  grid (16 jt, 16 it), block 256.
// Tile 64(i) x 64(j), 4x4/thread, packed f32x2 over k.
// ---------------------------------------------------------------------------
__global__ __launch_bounds__(256) void k3_pair(
    const int* __restrict__ perm, const float* __restrict__ W2,
    const float* __restrict__ b2g)
{
    __shared__ float2 Bys[64][17];
    __shared__ float2 Axs[64][17];
    __shared__ float2 w2s[160];
    __shared__ int    permS[64];
    __shared__ float  rowred[64][17];

    const int jt = blockIdx.x;   // 0..15
    const int it = blockIdx.y;   // 0..15
    const int i0 = it * 64, j0 = jt * 64;
    const int t  = threadIdx.x;
    const int tj = t & 15;       // j sub
    const int ti = t >> 4;       // i sub

    if (t < 64) permS[t] = perm[i0 + t];
    if (t < 160) {
        int k = 2 * t;
        w2s[t] = make_float2(k < MH ? W2[k] : 0.f,
                             k + 1 < MH ? W2[k + 1] : 0.f);
    }

    float2 acc[4][4];   // [r=i-sub][c=j-sub]
    #pragma unroll
    for (int r = 0; r < 4; ++r)
        #pragma unroll
        for (int c = 0; c < 4; ++c) acc[r][c] = make_float2(0.f, 0.f);

    for (int kk2 = 0; kk2 < 160; kk2 += 16) {
        __syncthreads();
        #pragma unroll
        for (int i = 0; i < 4; ++i) {
            int e = t + i * 256;
            int row = e >> 4, k2 = e & 15;
            int gk = (kk2 + k2) * 2;
            float2 zz = make_float2(0.f, 0.f);
            Bys[row][k2] = (gk < MH)
                ? *(const float2*)&g_By[permS[row] * OPAD + gk] : zz;
            Axs[row][k2] = (gk < MH)
                ? *(const float2*)&g_Axb[(j0 + row) * OPAD + gk] : zz;
        }
        __syncthreads();
        #pragma unroll 4
        for (int k2 = 0; k2 < 16; ++k2) {
            float2 wp = w2s[kk2 + k2];
            float2 a[4], b[4];
            #pragma unroll
            for (int c = 0; c < 4; ++c) a[c] = Axs[tj + 16 * c][k2];
            #pragma unroll
            for (int r = 0; r < 4; ++r) b[r] = Bys[ti + 16 * r][k2];
            #pragma unroll
            for (int r = 0; r < 4; ++r)
                #pragma unroll
                for (int c = 0; c < 4; ++c) {
                    float2 s = f2add(a[c], b[r]);
                    s.x = fmaxf(s.x, 0.f);
                    s.y = fmaxf(s.y, 0.f);
                    acc[r][c] = f2fma(s, wp, acc[r][c]);
                }
        }
    }

    const float b2v = b2g[0];
    __syncthreads();
    #pragma unroll
    for (int r = 0; r < 4; ++r) {
        float e = 0.f;
        #pragma unroll
        for (int c = 0; c < 4; ++c)
            e += expf(acc[r][c].x + acc[r][c].y + b2v);
        rowred[ti + 16 * r][tj] = e;
    }
    __syncthreads();
    if (t < 64) {
        float s = 0.f;
        #pragma unroll
        for (int c = 0; c < 16; ++c) s += rowred[t][c];
        g_rowpart[jt * B_SZ + i0 + t] = s;
    }
}

// ---------------------------------------------------------------------------
// K4: T0[b] = softplus( relu(Axb[b]+By[b]) . w2 + b2 )
// grid 256, block 128 (one warp per row), float2 loads.
// ---------------------------------------------------------------------------
__global__ __launch_bounds__(128) void k4_t0(
    const float* __restrict__ W2, const float* __restrict__ b2g)
{
    const int t = threadIdx.x;
    const int w = t >> 5, l = t & 31;
    const int b = blockIdx.x * 4 + w;
    float u = 0.f;
    for (int kp = l; kp < 150; kp += 32) {
        float2 ax = *(const float2*)&g_Axb[b * OPAD + 2 * kp];
        float2 by = *(const float2*)&g_By [b * OPAD + 2 * kp];
        float2 wv = ((const float2*)W2)[kp];
        u = fmaf(fmaxf(ax.x + by.x, 0.f), wv.x, u);
        u = fmaf(fmaxf(ax.y + by.y, 0.f), wv.y, u);
    }
    #pragma unroll
    for (int off = 16; off > 0; off >>= 1)
        u += __shfl_xor_sync(0xFFFFFFFFu, u, off);
    if (l == 0) g_T0[b] = softplusf(u + b2g[0]);
}

// ---------------------------------------------------------------------------
// K5: final scalar reduction (float logs, double grand sums)
// ---------------------------------------------------------------------------
__global__ __launch_bounds__(256) void k5_final(float* __restrict__ out)
{
    __shared__ double skl[8], st0[8], sL[8];
    const int t = threadIdx.x;
    double kl = 0.0, t0 = 0.0, L = 0.0;
    for (int i = t; i < B_SZ; i += 256) {
        kl += (double)g_klpart[i];
        t0 += (double)g_T0[i];
        float rs = 0.f;
        #pragma unroll
        for (int jt = 0; jt < 16; ++jt) rs += g_rowpart[jt * B_SZ + i];
        // logsumexp_j softplus(u) = log(B + sum_j e^u)
        L += (double)logf((float)B_SZ + rs);
    }
    #pragma unroll
    for (int off = 16; off > 0; off >>= 1) {
        kl += __shfl_xor_sync(0xFFFFFFFFu, kl, off);
        t0 += __shfl_xor_sync(0xFFFFFFFFu, t0, off);
        L  += __shfl_xor_sync(0xFFFFFFFFu, L,  off);
    }
    if ((t & 31) == 0) { skl[t >> 5] = kl; st0[t >> 5] = t0; sL[t >> 5] = L; }
    __syncthreads();
    if (t == 0) {
        double a = 0, b = 0, c = 0;
        #pragma unroll
        for (int i = 0; i < 8; ++i) { a += skl[i]; b += st0[i]; c += sL[i]; }
        double d_skl = a / (double)B_SZ * 0.5;
        double t0m   = b / (double)B_SZ;
        double meanL = c / (double)B_SZ;
        double lower = t0m - (meanL - log((double)B_SZ));
        out[0] = (float)(d_skl - lower);
    }
}

// ---------------------------------------------------------------------------
extern "C" void kernel_launch(void* const* d_in, const int* in_sizes, int n_in,
                              void* d_out, int out_size)
{
    const float* zl    = (const float*)d_in[0];
    const float* zv    = (const float*)d_in[1];
    const float* fclw  = (const float*)d_in[2];
    const float* fclb  = (const float*)d_in[3];
    const float* fcvw  = (const float*)d_in[4];
    const float* fcvb  = (const float*)d_in[5];
    const float* W1    = (const float*)d_in[6];
    const float* b1    = (const float*)d_in[7];
    const float* W2    = (const float*)d_in[8];
    const float* b2    = (const float*)d_in[9];
    const float* eps1  = (const float*)d_in[10];
    const float* eps2  = (const float*)d_in[11];
    const int*   perm  = (const int*)d_in[12];
    float* out = (float*)d_out;

    k1_fuse<<<B_SZ, 192>>>(zl, zv, fclw, fclb, fcvw, fcvb, eps1, eps2);
    k2_gemm<<<dim3(16, 5, 2), 256>>>(W1, b1);
    k3_pair<<<dim3(16, 16), 256>>>(perm, W2, b2);
    k4_t0<<<256, 128>>>(W2, b2);
    k5_final<<<1, 256>>>(out);
}

// round 4
// speedup vs baseline: 1.5552x; 1.3447x over previous
#include <cuda_runtime.h>
#include <math.h>

#define B_SZ   1024
#define HID    384
#define MH     300
#define OPAD   304

typedef unsigned long long u64;

// Scratch (device globals; allocations forbidden)
__device__ float g_s1[B_SZ * HID];
__device__ float g_s2[B_SZ * HID];
__device__ float g_Axb[B_SZ * OPAD];
__device__ float g_By [B_SZ * OPAD];
__device__ float g_klpart[B_SZ];
__device__ float g_T0[B_SZ];
__device__ float g_Lrow[B_SZ];
__device__ float g_rowpart[16 * B_SZ];

__device__ __forceinline__ float softplusf(float x) {
    return fmaxf(x, 0.f) + log1pf(expf(-fabsf(x)));
}

// Packed f32x2 ops on u64-resident data (no per-op pack/unpack movs)
__device__ __forceinline__ u64 f2add_u(u64 a, u64 b) {
    u64 d; asm("add.rn.f32x2 %0, %1, %2;" : "=l"(d) : "l"(a), "l"(b)); return d;
}
__device__ __forceinline__ u64 f2fma_u(u64 a, u64 b, u64 c) {
    u64 d; asm("fma.rn.f32x2 %0, %1, %2, %3;" : "=l"(d) : "l"(a), "l"(b), "l"(c)); return d;
}
__device__ __forceinline__ u64 f2relu_u(u64 a) {
    float lo, hi;
    asm("mov.b64 {%0,%1}, %2;" : "=f"(lo), "=f"(hi) : "l"(a));
    lo = fmaxf(lo, 0.f);
    hi = fmaxf(hi, 0.f);
    u64 d;
    asm("mov.b64 %0, {%1,%2};" : "=l"(d) : "f"(lo), "f"(hi));
    return d;
}
__device__ __forceinline__ float f2hsum(u64 a) {
    float lo, hi;
    asm("mov.b64 {%0,%1}, %2;" : "=f"(lo), "=f"(hi) : "l"(a));
    return lo + hi;
}

// ---------------------------------------------------------------------------
// K1: per-batch-row fused  einsum -> (mu,sig) -> sample -> KL partial
// grid 1024, block 192. HBM-bound (176 MB).
// ---------------------------------------------------------------------------
__global__ __launch_bounds__(192) void k1_fuse(
    const float* __restrict__ zl, const float* __restrict__ zv,
    const float* __restrict__ wl_g, const float* __restrict__ bl_g,
    const float* __restrict__ wv_g, const float* __restrict__ bv_g,
    const float* __restrict__ eps1, const float* __restrict__ eps2)
{
    __shared__ float z1s[768], z2s[768];
    __shared__ float wls[20], wvs[36];
    __shared__ float redw[6];
    const int b = blockIdx.x, t = threadIdx.x;
    if (t < 20) wls[t] = wl_g[t];
    if (t >= 32 && t < 68) wvs[t - 32] = wv_g[t - 32];
    __syncthreads();
    const float bl = bl_g[0], bv = bv_g[0];
    {
        const float4* p = (const float4*)(zl + (size_t)b * 20 * 768) + t;
        float4 a = make_float4(bl, bl, bl, bl);
        #pragma unroll
        for (int s = 0; s < 20; ++s) {
            float4 v = p[s * 192];
            float w = wls[s];
            a.x = fmaf(v.x, w, a.x); a.y = fmaf(v.y, w, a.y);
            a.z = fmaf(v.z, w, a.z); a.w = fmaf(v.w, w, a.w);
        }
        ((float4*)z1s)[t] = a;
    }
    {
        const float4* p = (const float4*)(zv + (size_t)b * 36 * 768) + t;
        float4 a = make_float4(bv, bv, bv, bv);
        #pragma unroll
        for (int s = 0; s < 36; ++s) {
            float4 v = p[s * 192];
            float w = wvs[s];
            a.x = fmaf(v.x, w, a.x); a.y = fmaf(v.y, w, a.y);
            a.z = fmaf(v.z, w, a.z); a.w = fmaf(v.w, w, a.w);
        }
        ((float4*)z2s)[t] = a;
    }
    __syncthreads();
    float klacc = 0.f;
    #pragma unroll
    for (int q = 0; q < 2; ++q) {
        int k = t + q * 192;
        float mu1 = z1s[k], mu2 = z2s[k];
        float sg1 = softplusf(z1s[k + HID]) + 1e-7f;
        float sg2 = softplusf(z2s[k + HID]) + 1e-7f;
        float e1 = eps1[b * HID + k], e2 = eps2[b * HID + k];
        float s1v = fmaf(sg1, e1, mu1);
        float s2v = fmaf(sg2, e2, mu2);
        g_s1[b * HID + k] = s1v;
        g_s2[b * HID + k] = s2v;
        float d1 = (s1v - mu2) / sg2;
        float d2 = (s2v - mu1) / sg1;
        klacc += 0.5f * (d1 * d1 + d2 * d2 - e1 * e1 - e2 * e2);
    }
    #pragma unroll
    for (int off = 16; off > 0; off >>= 1)
        klacc += __shfl_xor_sync(0xFFFFFFFFu, klacc, off);
    if ((t & 31) == 0) redw[t >> 5] = klacc;
    __syncthreads();
    if (t == 0)
        g_klpart[b] = redw[0] + redw[1] + redw[2] + redw[3] + redw[4] + redw[5];
}

// ---------------------------------------------------------------------------
// K2: Axb = s1 @ W1x^T + b1 ;  By = s2 @ W1y^T
// grid (16,5,2), block 256.  Tile 64x64, u64-packed over k, 4x4/thread.
// ---------------------------------------------------------------------------
__global__ __launch_bounds__(256) void k2_gemm(
    const float* __restrict__ W1, const float* __restrict__ b1)
{
    __shared__ u64 As[64][17];
    __shared__ u64 Ws[64][17];

    const int z  = blockIdx.z;
    const int r0 = blockIdx.x * 64;
    const int c0 = blockIdx.y * 64;
    const float* S = z ? g_s2 : g_s1;
    float*       O = z ? g_By : g_Axb;
    const int koff = z ? HID : 0;

    const int t  = threadIdx.x;
    const int tj = t & 15;
    const int ti = t >> 4;

    u64 acc[4][4];
    #pragma unroll
    for (int r = 0; r < 4; ++r)
        #pragma unroll
        for (int c = 0; c < 4; ++c) acc[r][c] = 0ull;

    for (int kk2 = 0; kk2 < 192; kk2 += 16) {
        __syncthreads();
        #pragma unroll
        for (int i = 0; i < 4; ++i) {
            int e = t + i * 256;
            int row = e >> 4, k2 = e & 15;
            As[row][k2] = *(const u64*)&S[(r0 + row) * HID + (kk2 + k2) * 2];
            int col = c0 + row;
            Ws[row][k2] = (col < MH)
                ? *(const u64*)&W1[col * 768 + koff + (kk2 + k2) * 2] : 0ull;
        }
        __syncthreads();
        #pragma unroll 4
        for (int k2 = 0; k2 < 16; ++k2) {
            u64 a[4], w[4];
            #pragma unroll
            for (int r = 0; r < 4; ++r) a[r] = As[ti + 16 * r][k2];
            #pragma unroll
            for (int c = 0; c < 4; ++c) w[c] = Ws[tj + 16 * c][k2];
            #pragma unroll
            for (int r = 0; r < 4; ++r)
                #pragma unroll
                for (int c = 0; c < 4; ++c)
                    acc[r][c] = f2fma_u(a[r], w[c], acc[r][c]);
        }
    }
    #pragma unroll
    for (int r = 0; r < 4; ++r) {
        int row = r0 + ti + 16 * r;
        #pragma unroll
        for (int c = 0; c < 4; ++c) {
            int col = c0 + tj + 16 * c;
            if (col < MH) {
                float v = f2hsum(acc[r][c]);
                if (z == 0) v += b1[col];
                O[row * OPAD + col] = v;
            }
        }
    }
}

// ---------------------------------------------------------------------------
// K3: pairwise grid.  u[i][j] = sum_k relu(Axb[j,k] + By[perm[i],k]) * w2[k]
// per-(i, jtile) partial sums of exp(u+b2).  grid (16,16), block 256.
// Tile 64(i) x 64(j), 4x4/thread, u64-packed over k.
// ---------------------------------------------------------------------------
__global__ __launch_bounds__(256) void k3_pair(
    const int* __restrict__ perm, const float* __restrict__ W2,
    const float* __restrict__ b2g)
{
    __shared__ u64 Bys[64][17];
    __shared__ u64 Axs[64][17];
    __shared__ u64 w2s[160];
    __shared__ int permS[64];
    __shared__ float rowred[64][17];

    const int jt = blockIdx.x;
    const int it = blockIdx.y;
    const int i0 = it * 64, j0 = jt * 64;
    const int t  = threadIdx.x;
    const int tj = t & 15;
    const int ti = t >> 4;

    if (t < 64) permS[t] = perm[i0 + t];
    if (t < 160) {
        int k = 2 * t;
        float2 w = make_float2(k < MH ? W2[k] : 0.f,
                               k + 1 < MH ? W2[k + 1] : 0.f);
        w2s[t] = *(const u64*)&w;
    }

    u64 acc[4][4];
    #pragma unroll
    for (int r = 0; r < 4; ++r)
        #pragma unroll
        for (int c = 0; c < 4; ++c) acc[r][c] = 0ull;

    for (int kk2 = 0; kk2 < 160; kk2 += 16) {
        __syncthreads();
        #pragma unroll
        for (int i = 0; i < 4; ++i) {
            int e = t + i * 256;
            int row = e >> 4, k2 = e & 15;
            int gk = (kk2 + k2) * 2;
            Bys[row][k2] = (gk < MH)
                ? *(const u64*)&g_By[permS[row] * OPAD + gk] : 0ull;
            Axs[row][k2] = (gk < MH)
                ? *(const u64*)&g_Axb[(j0 + row) * OPAD + gk] : 0ull;
        }
        __syncthreads();
        #pragma unroll 4
        for (int k2 = 0; k2 < 16; ++k2) {
            u64 wp = w2s[kk2 + k2];
            u64 a[4], b[4];
            #pragma unroll
            for (int c = 0; c < 4; ++c) a[c] = Axs[tj + 16 * c][k2];
            #pragma unroll
            for (int r = 0; r < 4; ++r) b[r] = Bys[ti + 16 * r][k2];
            #pragma unroll
            for (int r = 0; r < 4; ++r)
                #pragma unroll
                for (int c = 0; c < 4; ++c)
                    acc[r][c] = f2fma_u(f2relu_u(f2add_u(a[c], b[r])), wp,
                                        acc[r][c]);
        }
    }

    const float b2v = b2g[0];
    __syncthreads();
    #pragma unroll
    for (int r = 0; r < 4; ++r) {
        float e = 0.f;
        #pragma unroll
        for (int c = 0; c < 4; ++c)
            e += expf(f2hsum(acc[r][c]) + b2v);
        rowred[ti + 16 * r][tj] = e;
    }
    __syncthreads();
    if (t < 64) {
        float s = 0.f;
        #pragma unroll
        for (int c = 0; c < 16; ++c) s += rowred[t][c];
        g_rowpart[jt * B_SZ + i0 + t] = s;
    }
}

// ---------------------------------------------------------------------------
// K5a: per-row tail.  warp per row: T0[b] (dot) AND Lrow[b] = log(B + sum e^u)
// grid 128, block 256 (8 warps = 8 rows/block)
// ---------------------------------------------------------------------------
__global__ __launch_bounds__(256) void k5a_row(
    const float* __restrict__ W2, const float* __restrict__ b2g)
{
    const int t = threadIdx.x;
    const int w = t >> 5, l = t & 31;
    const int b = blockIdx.x * 8 + w;
    float u = 0.f;
    for (int kp = l; kp < 150; kp += 32) {
        float2 ax = *(const float2*)&g_Axb[b * OPAD + 2 * kp];
        float2 by = *(const float2*)&g_By [b * OPAD + 2 * kp];
        float2 wv = ((const float2*)W2)[kp];
        u = fmaf(fmaxf(ax.x + by.x, 0.f), wv.x, u);
        u = fmaf(fmaxf(ax.y + by.y, 0.f), wv.y, u);
    }
    float rs = (l < 16) ? g_rowpart[l * B_SZ + b] : 0.f;
    #pragma unroll
    for (int off = 16; off > 0; off >>= 1) {
        u  += __shfl_xor_sync(0xFFFFFFFFu, u,  off);
        rs += __shfl_xor_sync(0xFFFFFFFFu, rs, off);
    }
    if (l == 0) {
        g_T0[b]   = softplusf(u + b2g[0]);
        // logsumexp_j softplus(u) = log(B + sum_j e^u)
        g_Lrow[b] = logf((float)B_SZ + rs);
    }
}

// ---------------------------------------------------------------------------
// K5b: final scalar reduction
// ---------------------------------------------------------------------------
__global__ __launch_bounds__(256) void k5b_final(float* __restrict__ out)
{
    __shared__ double skl[8], st0[8], sL[8];
    const int t = threadIdx.x;
    double kl = 0.0, t0 = 0.0, L = 0.0;
    for (int i = t; i < B_SZ; i += 256) {
        kl += (double)g_klpart[i];
        t0 += (double)g_T0[i];
        L  += (double)g_Lrow[i];
    }
    #pragma unroll
    for (int off = 16; off > 0; off >>= 1) {
        kl += __shfl_xor_sync(0xFFFFFFFFu, kl, off);
        t0 += __shfl_xor_sync(0xFFFFFFFFu, t0, off);
        L  += __shfl_xor_sync(0xFFFFFFFFu, L,  off);
    }
    if ((t & 31) == 0) { skl[t >> 5] = kl; st0[t >> 5] = t0; sL[t >> 5] = L; }
    __syncthreads();
    if (t == 0) {
        double a = 0, b = 0, c = 0;
        #pragma unroll
        for (int i = 0; i < 8; ++i) { a += skl[i]; b += st0[i]; c += sL[i]; }
        double d_skl = a / (double)B_SZ * 0.5;
        double t0m   = b / (double)B_SZ;
        double meanL = c / (double)B_SZ;
        double lower = t0m - (meanL - log((double)B_SZ));
        out[0] = (float)(d_skl - lower);
    }
}

// ---------------------------------------------------------------------------
extern "C" void kernel_launch(void* const* d_in, const int* in_sizes, int n_in,
                              void* d_out, int out_size)
{
    const float* zl    = (const float*)d_in[0];
    const float* zv    = (const float*)d_in[1];
    const float* fclw  = (const float*)d_in[2];
    const float* fclb  = (const float*)d_in[3];
    const float* fcvw  = (const float*)d_in[4];
    const float* fcvb  = (const float*)d_in[5];
    const float* W1    = (const float*)d_in[6];
    const float* b1    = (const float*)d_in[7];
    const float* W2    = (const float*)d_in[8];
    const float* b2    = (const float*)d_in[9];
    const float* eps1  = (const float*)d_in[10];
    const float* eps2  = (const float*)d_in[11];
    const int*   perm  = (const int*)d_in[12];
    float* out = (float*)d_out;

    k1_fuse<<<B_SZ, 192>>>(zl, zv, fclw, fclb, fcvw, fcvb, eps1, eps2);
    k2_gemm<<<dim3(16, 5, 2), 256>>>(W1, b1);
    k3_pair<<<dim3(16, 16), 256>>>(perm, W2, b2);
    k5a_row<<<128, 256>>>(W2, b2);
    k5b_final<<<1, 256>>>(out);
}

// round 5
// speedup vs baseline: 1.7555x; 1.1287x over previous
#include <cuda_runtime.h>
#include <math.h>

#define B_SZ   1024
#define HID    384
#define MH     300
#define OPAD   320   // padded row stride; cols 300..319 stay zero (zero-init globals)

typedef unsigned long long u64;

// Scratch (device globals; allocations forbidden). Zero-initialized at load;
// padding columns are never written, so they remain exactly 0.0f.
__device__ float g_s1[B_SZ * HID];
__device__ float g_s2[B_SZ * HID];
__device__ float g_Axb[B_SZ * OPAD];
__device__ float g_By [B_SZ * OPAD];
__device__ float g_klpart[B_SZ];
__device__ float g_T0[B_SZ];
__device__ float g_rowpart[16 * B_SZ];

__device__ __forceinline__ float softplusf(float x) {
    return fmaxf(x, 0.f) + log1pf(expf(-fabsf(x)));
}

// Packed f32x2 ops on u64-resident data
__device__ __forceinline__ u64 f2add_u(u64 a, u64 b) {
    u64 d; asm("add.rn.f32x2 %0, %1, %2;" : "=l"(d) : "l"(a), "l"(b)); return d;
}
__device__ __forceinline__ u64 f2fma_u(u64 a, u64 b, u64 c) {
    u64 d; asm("fma.rn.f32x2 %0, %1, %2, %3;" : "=l"(d) : "l"(a), "l"(b), "l"(c)); return d;
}
__device__ __forceinline__ u64 f2relu_u(u64 a) {
    float lo, hi;
    asm("mov.b64 {%0,%1}, %2;" : "=f"(lo), "=f"(hi) : "l"(a));
    lo = fmaxf(lo, 0.f);
    hi = fmaxf(hi, 0.f);
    u64 d;
    asm("mov.b64 %0, {%1,%2};" : "=l"(d) : "f"(lo), "f"(hi));
    return d;
}
__device__ __forceinline__ float f2hsum(u64 a) {
    float lo, hi;
    asm("mov.b64 {%0,%1}, %2;" : "=f"(lo), "=f"(hi) : "l"(a));
    return lo + hi;
}
__device__ __forceinline__ u64 fpack(float x, float y) {
    u64 d; asm("mov.b64 %0, {%1,%2};" : "=l"(d) : "f"(x), "f"(y)); return d;
}

// ---------------------------------------------------------------------------
// K1: per-batch-row fused  einsum -> (mu,sig) -> sample -> KL partial
// grid 1024, block 192. HBM-bound (176 MB).
// ---------------------------------------------------------------------------
__global__ __launch_bounds__(192) void k1_fuse(
    const float* __restrict__ zl, const float* __restrict__ zv,
    const float* __restrict__ wl_g, const float* __restrict__ bl_g,
    const float* __restrict__ wv_g, const float* __restrict__ bv_g,
    const float* __restrict__ eps1, const float* __restrict__ eps2)
{
    __shared__ float z1s[768], z2s[768];
    __shared__ float wls[20], wvs[36];
    __shared__ float redw[6];
    const int b = blockIdx.x, t = threadIdx.x;
    if (t < 20) wls[t] = wl_g[t];
    if (t >= 32 && t < 68) wvs[t - 32] = wv_g[t - 32];
    __syncthreads();
    const float bl = bl_g[0], bv = bv_g[0];
    {
        const float4* p = (const float4*)(zl + (size_t)b * 20 * 768) + t;
        float4 a = make_float4(bl, bl, bl, bl);
        #pragma unroll
        for (int s = 0; s < 20; ++s) {
            float4 v = p[s * 192];
            float w = wls[s];
            a.x = fmaf(v.x, w, a.x); a.y = fmaf(v.y, w, a.y);
            a.z = fmaf(v.z, w, a.z); a.w = fmaf(v.w, w, a.w);
        }
        ((float4*)z1s)[t] = a;
    }
    {
        const float4* p = (const float4*)(zv + (size_t)b * 36 * 768) + t;
        float4 a = make_float4(bv, bv, bv, bv);
        #pragma unroll
        for (int s = 0; s < 36; ++s) {
            float4 v = p[s * 192];
            float w = wvs[s];
            a.x = fmaf(v.x, w, a.x); a.y = fmaf(v.y, w, a.y);
            a.z = fmaf(v.z, w, a.z); a.w = fmaf(v.w, w, a.w);
        }
        ((float4*)z2s)[t] = a;
    }
    __syncthreads();
    float klacc = 0.f;
    #pragma unroll
    for (int q = 0; q < 2; ++q) {
        int k = t + q * 192;
        float mu1 = z1s[k], mu2 = z2s[k];
        float sg1 = softplusf(z1s[k + HID]) + 1e-7f;
        float sg2 = softplusf(z2s[k + HID]) + 1e-7f;
        float e1 = eps1[b * HID + k], e2 = eps2[b * HID + k];
        float s1v = fmaf(sg1, e1, mu1);
        float s2v = fmaf(sg2, e2, mu2);
        g_s1[b * HID + k] = s1v;
        g_s2[b * HID + k] = s2v;
        float d1 = (s1v - mu2) / sg2;
        float d2 = (s2v - mu1) / sg1;
        klacc += 0.5f * (d1 * d1 + d2 * d2 - e1 * e1 - e2 * e2);
    }
    #pragma unroll
    for (int off = 16; off > 0; off >>= 1)
        klacc += __shfl_xor_sync(0xFFFFFFFFu, klacc, off);
    if ((t & 31) == 0) redw[t >> 5] = klacc;
    __syncthreads();
    if (t == 0)
        g_klpart[b] = redw[0] + redw[1] + redw[2] + redw[3] + redw[4] + redw[5];
}

// ---------------------------------------------------------------------------
// K2: Axb = s1 @ W1x^T + b1 ;  By = s2 @ W1y^T
// grid (16,5,2), block 256.  Tile 64x64, u64-packed over k, 4x4/thread.
// ---------------------------------------------------------------------------
__global__ __launch_bounds__(256) void k2_gemm(
    const float* __restrict__ W1, const float* __restrict__ b1)
{
    __shared__ u64 As[64][17];
    __shared__ u64 Ws[64][17];

    const int z  = blockIdx.z;
    const int r0 = blockIdx.x * 64;
    const int c0 = blockIdx.y * 64;
    const float* S = z ? g_s2 : g_s1;
    float*       O = z ? g_By : g_Axb;
    const int koff = z ? HID : 0;

    const int t  = threadIdx.x;
    const int tj = t & 15;
    const int ti = t >> 4;

    u64 acc[4][4];
    #pragma unroll
    for (int r = 0; r < 4; ++r)
        #pragma unroll
        for (int c = 0; c < 4; ++c) acc[r][c] = 0ull;

    for (int kk2 = 0; kk2 < 192; kk2 += 16) {
        __syncthreads();
        #pragma unroll
        for (int i = 0; i < 4; ++i) {
            int e = t + i * 256;
            int row = e >> 4, k2 = e & 15;
            As[row][k2] = *(const u64*)&S[(r0 + row) * HID + (kk2 + k2) * 2];
            int col = c0 + row;
            Ws[row][k2] = (col < MH)
                ? *(const u64*)&W1[col * 768 + koff + (kk2 + k2) * 2] : 0ull;
        }
        __syncthreads();
        #pragma unroll 4
        for (int k2 = 0; k2 < 16; ++k2) {
            u64 a[4], w[4];
            #pragma unroll
            for (int r = 0; r < 4; ++r) a[r] = As[ti + 16 * r][k2];
            #pragma unroll
            for (int c = 0; c < 4; ++c) w[c] = Ws[tj + 16 * c][k2];
            #pragma unroll
            for (int r = 0; r < 4; ++r)
                #pragma unroll
                for (int c = 0; c < 4; ++c)
                    acc[r][c] = f2fma_u(a[r], w[c], acc[r][c]);
        }
    }
    #pragma unroll
    for (int r = 0; r < 4; ++r) {
        int row = r0 + ti + 16 * r;
        #pragma unroll
        for (int c = 0; c < 4; ++c) {
            int col = c0 + tj + 16 * c;
            if (col < MH) {
                float v = f2hsum(acc[r][c]);
                if (z == 0) v += b1[col];
                O[row * OPAD + col] = v;
            }
        }
    }
}

// ---------------------------------------------------------------------------
// K3: pairwise grid (perm dropped — mean over i is bijection-invariant).
// u[i][j] = sum_k relu(Axb[j,k] + By[i,k]) * w2[k]
// Writes per-(i, jtile) partial sums of exp(u+b2); diagonal blocks also
// write T0[i] = softplus(u[i][i] + b2).
// grid (16 jt, 16 it), block 256.  64x64 tile, 4x4/thread, u64-packed,
// register-prefetch software pipeline over 10 k-chunks.
// ---------------------------------------------------------------------------
__global__ __launch_bounds__(256) void k3_pair(
    const float* __restrict__ W2, const float* __restrict__ b2g)
{
    __shared__ u64 Bys[64][17];
    __shared__ u64 Axs[64][17];
    __shared__ u64 w2s[160];
    __shared__ float rowred[64][17];

    const int jt = blockIdx.x;
    const int it = blockIdx.y;
    const int i0 = it * 64, j0 = jt * 64;
    const int t  = threadIdx.x;
    const int tj = t & 15;
    const int ti = t >> 4;

    if (t < 160) {
        int k = 2 * t;
        float2 w = make_float2(k < MH ? W2[k] : 0.f,
                               k + 1 < MH ? W2[k + 1] : 0.f);
        w2s[t] = *(const u64*)&w;
    }

    // float4 prefetch mapping: unit u in [0,512): row=u>>3, f4=u&7
    const int rA = t >> 3,          fA = t & 7;          // unit t
    const int rB = (t + 256) >> 3,  fB = t & 7;          // unit t+256
    const float* byA = &g_By [(i0 + rA) * OPAD + fA * 4];
    const float* byB = &g_By [(i0 + rB) * OPAD + fB * 4];
    const float* axA = &g_Axb[(j0 + rA) * OPAD + fA * 4];
    const float* axB = &g_Axb[(j0 + rB) * OPAD + fB * 4];

    u64 acc[4][4];
    #pragma unroll
    for (int r = 0; r < 4; ++r)
        #pragma unroll
        for (int c = 0; c < 4; ++c) acc[r][c] = 0ull;

    // prefetch chunk 0
    float4 pb0 = *(const float4*)(byA);
    float4 pb1 = *(const float4*)(byB);
    float4 pa0 = *(const float4*)(axA);
    float4 pa1 = *(const float4*)(axB);

    for (int c = 0; c < 10; ++c) {
        __syncthreads();   // previous compute done reading smem
        Bys[rA][2 * fA]     = fpack(pb0.x, pb0.y);
        Bys[rA][2 * fA + 1] = fpack(pb0.z, pb0.w);
        Bys[rB][2 * fB]     = fpack(pb1.x, pb1.y);
        Bys[rB][2 * fB + 1] = fpack(pb1.z, pb1.w);
        Axs[rA][2 * fA]     = fpack(pa0.x, pa0.y);
        Axs[rA][2 * fA + 1] = fpack(pa0.z, pa0.w);
        Axs[rB][2 * fB]     = fpack(pa1.x, pa1.y);
        Axs[rB][2 * fB + 1] = fpack(pa1.z, pa1.w);
        __syncthreads();
        if (c < 9) {
            int off = (c + 1) * 32;
            pb0 = *(const float4*)(byA + off);
            pb1 = *(const float4*)(byB + off);
            pa0 = *(const float4*)(axA + off);
            pa1 = *(const float4*)(axB + off);
        }
        #pragma unroll 4
        for (int k2 = 0; k2 < 16; ++k2) {
            u64 wp = w2s[c * 16 + k2];
            u64 a[4], b[4];
            #pragma unroll
            for (int cc = 0; cc < 4; ++cc) a[cc] = Axs[tj + 16 * cc][k2];
            #pragma unroll
            for (int r = 0; r < 4; ++r) b[r] = Bys[ti + 16 * r][k2];
            #pragma unroll
            for (int r = 0; r < 4; ++r)
                #pragma unroll
                for (int cc = 0; cc < 4; ++cc)
                    acc[r][cc] = f2fma_u(f2relu_u(f2add_u(a[cc], b[r])), wp,
                                         acc[r][cc]);
        }
    }

    const float b2v = b2g[0];

    // Diagonal blocks: T0[i] = softplus(u[i][i] + b2)
    if (jt == it && tj == ti) {
        #pragma unroll
        for (int r = 0; r < 4; ++r)
            g_T0[i0 + ti + 16 * r] = softplusf(f2hsum(acc[r][r]) + b2v);
    }

    __syncthreads();
    #pragma unroll
    for (int r = 0; r < 4; ++r) {
        float e = 0.f;
        #pragma unroll
        for (int cc = 0; cc < 4; ++cc)
            e += expf(f2hsum(acc[r][cc]) + b2v);
        rowred[ti + 16 * r][tj] = e;
    }
    __syncthreads();
    if (t < 64) {
        float s = 0.f;
        #pragma unroll
        for (int cc = 0; cc < 16; ++cc) s += rowred[t][cc];
        g_rowpart[jt * B_SZ + i0 + t] = s;
    }
}

// ---------------------------------------------------------------------------
// K5: final reduction.  1024 threads, one row each.
// ---------------------------------------------------------------------------
__global__ __launch_bounds__(1024) void k5_final(float* __restrict__ out)
{
    __shared__ double skl[32], st0[32], sL[32];
    const int t = threadIdx.x;
    float rs = 0.f;
    #pragma unroll
    for (int jt = 0; jt < 16; ++jt) rs += g_rowpart[jt * B_SZ + t];
    // logsumexp_j softplus(u) = log(B + sum_j e^u)
    double kl = (double)g_klpart[t];
    double t0 = (double)g_T0[t];
    double L  = (double)logf((float)B_SZ + rs);
    #pragma unroll
    for (int off = 16; off > 0; off >>= 1) {
        kl += __shfl_xor_sync(0xFFFFFFFFu, kl, off);
        t0 += __shfl_xor_sync(0xFFFFFFFFu, t0, off);
        L  += __shfl_xor_sync(0xFFFFFFFFu, L,  off);
    }
    if ((t & 31) == 0) { skl[t >> 5] = kl; st0[t >> 5] = t0; sL[t >> 5] = L; }
    __syncthreads();
    if (t < 32) {
        kl = skl[t]; t0 = st0[t]; L = sL[t];
        #pragma unroll
        for (int off = 16; off > 0; off >>= 1) {
            kl += __shfl_xor_sync(0xFFFFFFFFu, kl, off);
            t0 += __shfl_xor_sync(0xFFFFFFFFu, t0, off);
            L  += __shfl_xor_sync(0xFFFFFFFFu, L,  off);
        }
        if (t == 0) {
            double d_skl = kl / (double)B_SZ * 0.5;
            double t0m   = t0 / (double)B_SZ;
            double meanL = L  / (double)B_SZ;
            double lower = t0m - (meanL - log((double)B_SZ));
            out[0] = (float)(d_skl - lower);
        }
    }
}

// ---------------------------------------------------------------------------
extern "C" void kernel_launch(void* const* d_in, const int* in_sizes, int n_in,
                              void* d_out, int out_size)
{
    const float* zl    = (const float*)d_in[0];
    const float* zv    = (const float*)d_in[1];
    const float* fclw  = (const float*)d_in[2];
    const float* fclb  = (const float*)d_in[3];
    const float* fcvw  = (const float*)d_in[4];
    const float* fcvb  = (const float*)d_in[5];
    const float* W1    = (const float*)d_in[6];
    const float* b1    = (const float*)d_in[7];
    const float* W2    = (const float*)d_in[8];
    const float* b2    = (const float*)d_in[9];
    const float* eps1  = (const float*)d_in[10];
    const float* eps2  = (const float*)d_in[11];
    float* out = (float*)d_out;

    k1_fuse<<<B_SZ, 192>>>(zl, zv, fclw, fclb, fcvw, fcvb, eps1, eps2);
    k2_gemm<<<dim3(16, 5, 2), 256>>>(W1, b1);
    k3_pair<<<dim3(16, 16), 256>>>(W2, b2);
    k5_final<<<1, 1024>>>(out);
}